// round 3
// baseline (speedup 1.0000x reference)
#include <cuda_runtime.h>
#include <cuda_bf16.h>
#include <cstdint>

// ExpertCapacityBuffer: N tokens, TOP_K=2, 64 experts.
// capacity = ceil(1.25 * N * 2 / 64). Flat order slot-major: f = slot*N + tok.
// rank(f) = #{g < f : expert(g)==expert(f)}; keep iff rank < capacity.
//
// Single-pass design: each block owns EPB contiguous flat positions.
//   phase 1: warp match-any ranks + block histogram; publish counts (release flag1)
//   phase 2: lookback-sum counts of all predecessor blocks (backward-only wait)
//   phase 3: write capped weights (+indices); first-half blocks release flag2
//   phase 4: second-half blocks (slot1 token range == partner's slot0 range)
//            wait partner flag2, compute per-token overflow mask in-block.

#define NE   64
#define TPB  512
#define EPB  1024          // flat elements per block
#define MAXB 1024          // supports flat up to 1M

__device__ int g_counts[MAXB][NE];
__device__ int g_flag1[MAXB];
__device__ int g_flag2[MAXB];

__device__ __forceinline__ int ld_acq(const int* p) {
    int v;
    asm volatile("ld.acquire.gpu.b32 %0, [%1];" : "=r"(v) : "l"(p) : "memory");
    return v;
}
__device__ __forceinline__ void st_rel(int* p, int v) {
    asm volatile("st.release.gpu.b32 [%0], %1;" :: "l"(p), "r"(v) : "memory");
}

__global__ void k_init(int nb) {
    int t = threadIdx.x;
    for (int i = t; i < nb; i += TPB) { g_flag1[i] = 0; g_flag2[i] = 0; }
}

__global__ void __launch_bounds__(TPB)
k_main(const float* __restrict__ w, const void* __restrict__ eraw,
       int n_tok, int flat, int capacity, int nb, int nb_half,
       float* __restrict__ out_w, float* __restrict__ out_idx, int idx_mode,
       float* __restrict__ out_mask, int inline_mask) {
    __shared__ int whist[32][NE];   // 32 warp-rounds x 64 experts (8KB)
    __shared__ int s_part[8][NE];   // lookback partials (2KB)
    __shared__ int s_base[NE];
    __shared__ int s_is64;

    const int t = threadIdx.x, b = blockIdx.x;
    const int warp = t >> 5, lane = t & 31;

    // ---- dtype probe: odd 32-bit words of first 512 words (safe for int32 min size)
    if (t == 0) s_is64 = 1;
    for (int i = t; i < 32 * NE; i += TPB) ((int*)whist)[i] = 0;
    __syncthreads();
    if (t < 256) {
        unsigned v = ((const unsigned*)eraw)[2 * t + 1];
        if (v != 0u) atomicAnd(&s_is64, 0);
    }
    __syncthreads();
    const bool is64 = (s_is64 != 0);

    // ---- phase 1: load, match ranks, block histogram
    int   e[2], wrank[2], pos[2];
    float wv[2];
    bool  val[2];
    #pragma unroll
    for (int r = 0; r < 2; r++) {
        int p = r * TPB + t;
        int f = b * EPB + p;                 // flat index (fits int for our sizes)
        bool v = f < flat;
        int slot = 0, tok = 0;
        if (v) { slot = (f >= n_tok) ? 1 : 0; tok = f - slot * n_tok; }
        int idx = tok * 2 + slot;
        int ee = NE + lane;                  // unique key for invalid lanes
        if (v) ee = (is64 ? (int)((const long long*)eraw)[idx]
                          : ((const int*)eraw)[idx]) & (NE - 1);
        unsigned m  = __match_any_sync(0xFFFFFFFFu, ee);
        int      wr = __popc(m & ((1u << lane) - 1u));
        if (v && wr == 0) whist[r * 16 + warp][ee] = __popc(m);
        e[r] = ee; wrank[r] = wr; pos[r] = idx; val[r] = v;
        wv[r] = v ? w[idx] : 0.0f;
    }
    __syncthreads();

    // exclusive scan down the 32 warp-rounds per expert; row sum = block count
    if (t < NE) {
        int run = 0;
        #pragma unroll
        for (int rr = 0; rr < 32; rr++) { int c = whist[rr][t]; whist[rr][t] = run; run += c; }
        g_counts[b][t] = run;
    }
    __syncthreads();
    if (t == 0) { __threadfence(); st_rel(&g_flag1[b], 1); }

    // ---- phase 2: lookback over predecessors (coalesced: e = t&63)
    {
        int ec = t & (NE - 1), chunk = t >> 6;   // 8 chunks
        int acc = 0;
        for (int s = chunk; s < b; s += 8) {
            if ((t & (NE - 1)) == 0) { /* no-op; every thread polls its own */ }
            while (ld_acq(&g_flag1[s]) == 0) { }
            acc += g_counts[s][ec];
        }
        s_part[chunk][ec] = acc;
    }
    __syncthreads();
    if (t < NE) {
        int v = 0;
        #pragma unroll
        for (int c = 0; c < 8; c++) v += s_part[c][t];
        s_base[t] = v;
    }
    __syncthreads();

    // ---- phase 3: apply capacity, write outputs
    #pragma unroll
    for (int r = 0; r < 2; r++) {
        if (val[r]) {
            int rank = s_base[e[r]] + whist[r * 16 + warp][e[r]] + wrank[r];
            out_w[pos[r]] = (rank < capacity) ? wv[r] : 0.0f;
            if (idx_mode == 1)      out_idx[pos[r]] = (float)e[r];
            else if (idx_mode == 2) ((long long*)out_idx)[pos[r]] = (long long)e[r];
        }
    }

    // ---- phase 4: overflow mask
    if (out_mask && inline_mask) {
        __syncthreads();
        if (b < nb_half) {
            if (t == 0) { __threadfence(); st_rel(&g_flag2[b], 1); }
        } else {
            if (t == 0) { while (ld_acq(&g_flag2[b - nb_half]) == 0) { } }
            __syncthreads();
            int tok0 = (b - nb_half) * EPB;
            for (int i = t; i < EPB; i += TPB) {
                int tok = tok0 + i;
                if (tok < n_tok) {
                    const float2* pw = (const float2*)out_w + tok;
                    float2 v2 = __ldcg(pw);
                    out_mask[tok] = ((v2.x + v2.y) == 0.0f) ? 1.0f : 0.0f;
                }
            }
        }
    }
}

// fallback mask kernel (only if token count not divisible by EPB)
__global__ void k_mask(const float* __restrict__ out_w, int n_tok,
                       float* __restrict__ out_mask) {
    int t = blockIdx.x * blockDim.x + threadIdx.x;
    if (t < n_tok) {
        float2 v = reinterpret_cast<const float2*>(out_w)[t];
        out_mask[t] = ((v.x + v.y) == 0.0f) ? 1.0f : 0.0f;
    }
}

extern "C" void kernel_launch(void* const* d_in, const int* in_sizes, int n_in,
                              void* d_out, int out_size) {
    const float* w    = (const float*)d_in[0];
    const void*  eidx = d_in[1];

    int flat  = in_sizes[0];                 // N * TOP_K
    int n_tok = flat / 2;
    int capacity = (flat * 5 + 255) / 256;   // ceil(1.25 * flat / 64)
    if (capacity < 1) capacity = 1;
    int nb = (flat + EPB - 1) / EPB;
    if (nb > MAXB) nb = MAXB;
    int nb_half = nb / 2;
    int inline_mask = (n_tok % EPB == 0) && (nb % 2 == 0);

    float* out = (float*)d_out;
    float* out_w    = out;
    float* out_idx  = nullptr;
    float* out_mask = nullptr;
    int idx_mode = 0;

    if (out_size >= 3 * flat + n_tok) {          // weights + i64 indices + mask
        idx_mode = 2; out_idx = out + flat; out_mask = out + 3 * flat;
    } else if (out_size >= 2 * flat + n_tok) {   // weights + 1-word indices + mask
        idx_mode = 1; out_idx = out + flat; out_mask = out + 2 * flat;
    } else if (out_size >= flat + n_tok) {       // weights + mask
        out_mask = out + flat;
    }

    k_init<<<1, TPB>>>(nb);
    k_main<<<nb, TPB>>>(w, eidx, n_tok, flat, capacity, nb, nb_half,
                        out_w, out_idx, idx_mode, out_mask, inline_mask);
    if (out_mask && !inline_mask)
        k_mask<<<(n_tok + 255) / 256, 256>>>(out_w, n_tok, out_mask);
}

// round 4
// speedup vs baseline: 2.5237x; 2.5237x over previous
#include <cuda_runtime.h>
#include <cuda_bf16.h>
#include <cstdint>

// ExpertCapacityBuffer: N tokens, TOP_K=2, 64 experts.
// capacity = ceil(1.25*N*2/64). Flat slot-major: f = slot*N + tok.
// rank(f) = #{g<f : expert(g)==expert(f)}; keep iff rank < capacity.
//
// Chunking: token blocks of EPT=1024. Count row r in [0,nbt) = slot0 tokens of
// block r (flat order); row nbt+r = slot1 tokens of block r. Row-major order
// over rows == flat order, so exclusive row prefixes give exact global ranks.

#define NE   64
#define TPB  1024
#define EPT  1024           // tokens per block
#define MAXROWS 4096        // supports n_tok up to 2M

__device__ int g_cnt[MAXROWS][NE];   // per-row expert counts
__device__ int g_off[MAXROWS][NE];   // exclusive prefixes

__device__ __forceinline__ bool probe_is64(const void* eraw, int flat) {
    // int64 values <64 => odd 32-bit words all zero. Check first 512 words
    // (safe: flat >= 512 in practice; guard anyway).
    const unsigned* r = (const unsigned*)eraw;
    int lim = (flat < 512) ? flat : 512;
    __shared__ int s64;
    if (threadIdx.x == 0) s64 = 1;
    __syncthreads();
    if (threadIdx.x < 256) {
        int i = 2 * threadIdx.x + 1;
        if (i < lim && r[i] != 0u) atomicAnd(&s64, 0);
    }
    __syncthreads();
    return s64 != 0;
}

// ---------------- Kernel 1: per-row expert histograms ----------------
__global__ void __launch_bounds__(TPB)
k_count(const void* __restrict__ eraw, int n_tok, int nbt) {
    __shared__ int hA[32][NE];      // slot0 warp hist
    __shared__ int hB[32][NE];      // slot1 warp hist
    const int t = threadIdx.x, b = blockIdx.x;
    const int warp = t >> 5, lane = t & 31;

    for (int i = t; i < 32 * NE; i += TPB) { ((int*)hA)[i] = 0; ((int*)hB)[i] = 0; }
    const bool is64 = probe_is64(eraw, 2 * n_tok);   // includes __syncthreads
    __syncthreads();

    int tok = b * EPT + t;
    bool valid = tok < n_tok;
    int e0 = NE + lane, e1 = NE + lane;
    if (valid) {
        if (is64) {
            longlong2 v = ((const longlong2*)eraw)[tok];
            e0 = (int)v.x & (NE - 1); e1 = (int)v.y & (NE - 1);
        } else {
            int2 v = ((const int2*)eraw)[tok];
            e0 = v.x & (NE - 1); e1 = v.y & (NE - 1);
        }
    }
    unsigned m0 = __match_any_sync(0xFFFFFFFFu, e0);
    unsigned m1 = __match_any_sync(0xFFFFFFFFu, e1);
    unsigned lt = (1u << lane) - 1u;
    if (valid && !(m0 & lt)) hA[warp][e0] = __popc(m0);
    if (valid && !(m1 & lt)) hB[warp][e1] = __popc(m1);
    __syncthreads();

    if (t < NE) {
        int s = 0;
        #pragma unroll
        for (int w = 0; w < 32; w++) s += hA[w][t];
        g_cnt[b][t] = s;
    } else if (t < 2 * NE) {
        int e = t - NE, s = 0;
        #pragma unroll
        for (int w = 0; w < 32; w++) s += hB[w][e];
        g_cnt[nbt + b][e] = s;
    }
}

// ---------------- Kernel 2: exclusive scan over rows, per expert ----------------
#define NCH 16
__global__ void __launch_bounds__(TPB)
k_scan(int rows) {
    __shared__ int part[NCH][NE];
    const int t = threadIdx.x;
    const int e = t & (NE - 1), c = t >> 6;      // 16 chunks x 64 experts
    const int rpc = (rows + NCH - 1) / NCH;
    const int r0 = c * rpc, r1 = min(r0 + rpc, rows);

    int s = 0;
    for (int r = r0; r < r1; r++) s += g_cnt[r][e];
    part[c][e] = s;
    __syncthreads();

    if (t < NE) {
        int run = 0;
        #pragma unroll
        for (int cc = 0; cc < NCH; cc++) { int v = part[cc][t]; part[cc][t] = run; run += v; }
    }
    __syncthreads();

    int run = part[c][e];
    for (int r = r0; r < r1; r++) { int v = g_cnt[r][e]; g_off[r][e] = run; run += v; }
}

// ---------------- Kernel 3: ranks, capped weights, indices, mask ----------------
// idx_mode: 0 none, 1 one-word (float), 2 int64
__global__ void __launch_bounds__(TPB)
k_apply(const float* __restrict__ w, const void* __restrict__ eraw,
        int n_tok, int capacity, int nbt,
        float* __restrict__ out_w, void* __restrict__ out_idx, int idx_mode,
        float* __restrict__ out_mask) {
    __shared__ int hA[32][NE];
    __shared__ int hB[32][NE];
    __shared__ int offA[NE], offB[NE];
    const int t = threadIdx.x, b = blockIdx.x;
    const int warp = t >> 5, lane = t & 31;

    for (int i = t; i < 32 * NE; i += TPB) { ((int*)hA)[i] = 0; ((int*)hB)[i] = 0; }
    const bool is64 = probe_is64(eraw, 2 * n_tok);
    if (t < NE)            offA[t] = g_off[b][t];
    else if (t < 2 * NE)   offB[t - NE] = g_off[nbt + b][t - NE];
    __syncthreads();

    int tok = b * EPT + t;
    bool valid = tok < n_tok;
    int e0 = NE + lane, e1 = NE + lane;
    float2 wv = make_float2(0.f, 0.f);
    if (valid) {
        if (is64) {
            longlong2 v = ((const longlong2*)eraw)[tok];
            e0 = (int)v.x & (NE - 1); e1 = (int)v.y & (NE - 1);
        } else {
            int2 v = ((const int2*)eraw)[tok];
            e0 = v.x & (NE - 1); e1 = v.y & (NE - 1);
        }
        wv = ((const float2*)w)[tok];
    }
    unsigned m0 = __match_any_sync(0xFFFFFFFFu, e0);
    unsigned m1 = __match_any_sync(0xFFFFFFFFu, e1);
    unsigned lt = (1u << lane) - 1u;
    int wr0 = __popc(m0 & lt), wr1 = __popc(m1 & lt);
    if (valid && wr0 == 0) hA[warp][e0] = __popc(m0);
    if (valid && wr1 == 0) hB[warp][e1] = __popc(m1);
    __syncthreads();

    // parallel exclusive scans down 32 warps: threads 0-63 slot0, 64-127 slot1
    if (t < NE) {
        int run = 0;
        #pragma unroll
        for (int ww = 0; ww < 32; ww++) { int v = hA[ww][t]; hA[ww][t] = run; run += v; }
    } else if (t < 2 * NE) {
        int e = t - NE, run = 0;
        #pragma unroll
        for (int ww = 0; ww < 32; ww++) { int v = hB[ww][e]; hB[ww][e] = run; run += v; }
    }
    __syncthreads();

    if (valid) {
        int rank0 = offA[e0] + hA[warp][e0] + wr0;
        int rank1 = offB[e1] + hB[warp][e1] + wr1;
        float w0 = (rank0 < capacity) ? wv.x : 0.0f;
        float w1 = (rank1 < capacity) ? wv.y : 0.0f;
        ((float2*)out_w)[tok] = make_float2(w0, w1);
        if (idx_mode == 1) {
            ((float2*)out_idx)[tok] = make_float2((float)e0, (float)e1);
        } else if (idx_mode == 2) {
            longlong2 iv; iv.x = e0; iv.y = e1;
            ((longlong2*)out_idx)[tok] = iv;
        }
        if (out_mask) out_mask[tok] = ((w0 + w1) == 0.0f) ? 1.0f : 0.0f;
    }
}

extern "C" void kernel_launch(void* const* d_in, const int* in_sizes, int n_in,
                              void* d_out, int out_size) {
    const float* w    = (const float*)d_in[0];
    const void*  eidx = d_in[1];

    int flat  = in_sizes[0];                 // N * TOP_K
    int n_tok = flat / 2;
    int capacity = (flat * 5 + 255) / 256;   // ceil(1.25 * flat / 64)
    if (capacity < 1) capacity = 1;
    int nbt = (n_tok + EPT - 1) / EPT;
    if (2 * nbt > MAXROWS) nbt = MAXROWS / 2;   // guard (not hit at these sizes)
    int rows = 2 * nbt;

    float* out = (float*)d_out;
    float* out_w    = out;
    void*  out_idx  = nullptr;
    float* out_mask = nullptr;
    int idx_mode = 0;

    if (out_size >= 3 * flat + n_tok) {          // weights + i64 indices + mask
        idx_mode = 2; out_idx = out + flat; out_mask = out + 3 * flat;
    } else if (out_size >= 2 * flat + n_tok) {   // weights + 1-word indices + mask
        idx_mode = 1; out_idx = out + flat; out_mask = out + 2 * flat;
    } else if (out_size >= flat + n_tok) {       // weights + mask
        out_mask = out + flat;
    }

    k_count<<<nbt, TPB>>>(eidx, n_tok, nbt);
    k_scan<<<1, TPB>>>(rows);
    k_apply<<<nbt, TPB>>>(w, eidx, n_tok, capacity, nbt,
                          out_w, out_idx, idx_mode, out_mask);
}

// round 5
// speedup vs baseline: 2.9275x; 1.1600x over previous
#include <cuda_runtime.h>
#include <cuda_bf16.h>
#include <cstdint>

// ExpertCapacityBuffer: N tokens, TOP_K=2, 64 experts.
// capacity = ceil(1.25*N*2/64). Flat slot-major: f = slot*N + tok.
// rank(f) = #{g<f : expert(g)==expert(f)}; keep iff rank < capacity.
//
// Rows of g_cnt: row r in [0,nbt) = slot0 of token-block r; row nbt+r = slot1
// of token-block r. Row-major row order == flat order.
// 2 kernels: count (histograms), apply (per-block prefix from g_cnt + output).

#define NE   64
#define TPB  1024
#define EPT  1024
#define MAXROWS 4096

__device__ int g_cnt[MAXROWS][NE];

// warp-0 dtype probe: int64 values <64 => odd 32-bit words zero.
// Reads first 256B of index buffer (always in-bounds).
__device__ __forceinline__ void probe_w0(const void* eraw, int lane, int* s_is64) {
    if (threadIdx.x < 32) {
        unsigned x = ((const unsigned*)eraw)[2 * lane + 1];
        unsigned nz = __ballot_sync(0xFFFFFFFFu, x != 0u);
        if (lane == 0) *s_is64 = (nz == 0u);
    }
}

// ---------------- Kernel 1: per-row expert histograms ----------------
__global__ void __launch_bounds__(TPB)
k_count(const void* __restrict__ eraw, int n_tok, int nbt) {
    __shared__ int hA[32][NE];
    __shared__ int hB[32][NE];
    __shared__ int s_is64;
    const int t = threadIdx.x, b = blockIdx.x;
    const int warp = t >> 5, lane = t & 31;

    const int tok = b * EPT + t;
    const bool valid = tok < n_tok;

    // eager int32-interpretation load (always in-bounds for either dtype)
    int2 v32 = make_int2(0, 0);
    if (valid) v32 = __ldg((const int2*)eraw + tok);

    // overlap: zero hists + probe while load is in flight
    ((int*)hA)[t] = 0; ((int*)hA)[t + TPB] = 0;
    ((int*)hB)[t] = 0; ((int*)hB)[t + TPB] = 0;
    probe_w0(eraw, lane, &s_is64);
    __syncthreads();

    int e0 = NE + lane, e1 = NE + lane;     // unique keys for invalid lanes
    if (valid) {
        if (s_is64) {
            longlong2 v = __ldg((const longlong2*)eraw + tok);
            e0 = (int)v.x & (NE - 1); e1 = (int)v.y & (NE - 1);
        } else {
            e0 = v32.x & (NE - 1); e1 = v32.y & (NE - 1);
        }
    }
    unsigned m0 = __match_any_sync(0xFFFFFFFFu, e0);
    unsigned m1 = __match_any_sync(0xFFFFFFFFu, e1);
    unsigned lt = (1u << lane) - 1u;
    if (valid && !(m0 & lt)) hA[warp][e0] = __popc(m0);
    if (valid && !(m1 & lt)) hB[warp][e1] = __popc(m1);
    __syncthreads();

    if (t < NE) {
        int s = 0;
        #pragma unroll
        for (int w = 0; w < 32; w++) s += hA[w][t];
        g_cnt[b][t] = s;
    } else if (t < 2 * NE) {
        const int e = t - NE;
        int s = 0;
        #pragma unroll
        for (int w = 0; w < 32; w++) s += hB[w][e];
        g_cnt[nbt + b][e] = s;
    }
}

// ---------------- Kernel 2: prefixes + ranks + outputs ----------------
// idx_mode: 0 none, 1 one-word (float), 2 int64
__global__ void __launch_bounds__(TPB)
k_apply(const float* __restrict__ w, const void* __restrict__ eraw,
        int n_tok, int capacity, int nbt,
        float* __restrict__ out_w, void* __restrict__ out_idx, int idx_mode,
        float* __restrict__ out_mask) {
    __shared__ int hA[32][NE];
    __shared__ int hB[32][NE];
    __shared__ int partA[16][NE];
    __shared__ int partB[16][NE];
    __shared__ int offA[NE], offB[NE];
    __shared__ int s_is64;
    const int t = threadIdx.x, b = blockIdx.x;
    const int warp = t >> 5, lane = t & 31;

    const int tok = b * EPT + t;
    const bool valid = tok < n_tok;

    // eager loads
    int2 v32 = make_int2(0, 0);
    float2 wv = make_float2(0.f, 0.f);
    if (valid) {
        v32 = __ldg((const int2*)eraw + tok);
        wv  = __ldg((const float2*)w + tok);
    }

    ((int*)hA)[t] = 0; ((int*)hA)[t + TPB] = 0;
    ((int*)hB)[t] = 0; ((int*)hB)[t + TPB] = 0;
    probe_w0(eraw, lane, &s_is64);

    // per-block prefix over g_cnt rows (slot0: rows [0,b); slot1: rows [0,nbt+b))
    {
        const int e = t & (NE - 1), c = t >> 6;   // 16 chunks x 64 experts
        int accA = 0, accB = 0;
        const int limB = nbt + b;
        for (int r = c; r < limB; r += 16) {
            int v = g_cnt[r][e];
            accB += v;
            if (r < b) accA += v;
        }
        partA[c][e] = accA;
        partB[c][e] = accB;
    }
    __syncthreads();

    int e0 = NE + lane, e1 = NE + lane;
    if (valid) {
        if (s_is64) {
            longlong2 v = __ldg((const longlong2*)eraw + tok);
            e0 = (int)v.x & (NE - 1); e1 = (int)v.y & (NE - 1);
        } else {
            e0 = v32.x & (NE - 1); e1 = v32.y & (NE - 1);
        }
    }
    unsigned m0 = __match_any_sync(0xFFFFFFFFu, e0);
    unsigned m1 = __match_any_sync(0xFFFFFFFFu, e1);
    unsigned lt = (1u << lane) - 1u;
    const int wr0 = __popc(m0 & lt), wr1 = __popc(m1 & lt);
    if (valid && wr0 == 0) hA[warp][e0] = __popc(m0);
    if (valid && wr1 == 0) hB[warp][e1] = __popc(m1);
    __syncthreads();

    // threads 0-63: slot0 scan + part reduce; 64-127: slot1
    if (t < NE) {
        int run = 0;
        #pragma unroll
        for (int ww = 0; ww < 32; ww++) { int v = hA[ww][t]; hA[ww][t] = run; run += v; }
        int s = 0;
        #pragma unroll
        for (int c = 0; c < 16; c++) s += partA[c][t];
        offA[t] = s;
    } else if (t < 2 * NE) {
        const int e = t - NE;
        int run = 0;
        #pragma unroll
        for (int ww = 0; ww < 32; ww++) { int v = hB[ww][e]; hB[ww][e] = run; run += v; }
        int s = 0;
        #pragma unroll
        for (int c = 0; c < 16; c++) s += partB[c][e];
        offB[e] = s;
    }
    __syncthreads();

    if (valid) {
        const int rank0 = offA[e0] + hA[warp][e0] + wr0;
        const int rank1 = offB[e1] + hB[warp][e1] + wr1;
        const float w0 = (rank0 < capacity) ? wv.x : 0.0f;
        const float w1 = (rank1 < capacity) ? wv.y : 0.0f;
        ((float2*)out_w)[tok] = make_float2(w0, w1);
        if (idx_mode == 1) {
            ((float2*)out_idx)[tok] = make_float2((float)e0, (float)e1);
        } else if (idx_mode == 2) {
            longlong2 iv; iv.x = e0; iv.y = e1;
            ((longlong2*)out_idx)[tok] = iv;
        }
        if (out_mask) out_mask[tok] = ((w0 + w1) == 0.0f) ? 1.0f : 0.0f;
    }
}

extern "C" void kernel_launch(void* const* d_in, const int* in_sizes, int n_in,
                              void* d_out, int out_size) {
    const float* w    = (const float*)d_in[0];
    const void*  eidx = d_in[1];

    int flat  = in_sizes[0];                 // N * TOP_K
    int n_tok = flat / 2;
    int capacity = (flat * 5 + 255) / 256;   // ceil(1.25 * flat / 64)
    if (capacity < 1) capacity = 1;
    int nbt = (n_tok + EPT - 1) / EPT;
    if (2 * nbt > MAXROWS) nbt = MAXROWS / 2;   // guard (not hit at these sizes)

    float* out = (float*)d_out;
    float* out_w    = out;
    void*  out_idx  = nullptr;
    float* out_mask = nullptr;
    int idx_mode = 0;

    if (out_size >= 3 * flat + n_tok) {          // weights + i64 indices + mask
        idx_mode = 2; out_idx = out + flat; out_mask = out + 3 * flat;
    } else if (out_size >= 2 * flat + n_tok) {   // weights + 1-word indices + mask
        idx_mode = 1; out_idx = out + flat; out_mask = out + 2 * flat;
    } else if (out_size >= flat + n_tok) {       // weights + mask
        out_mask = out + flat;
    }

    k_count<<<nbt, TPB>>>(eidx, n_tok, nbt);
    k_apply<<<nbt, TPB>>>(w, eidx, n_tok, capacity, nbt,
                          out_w, out_idx, idx_mode, out_mask);
}